// round 2
// baseline (speedup 1.0000x reference)
#include <cuda_runtime.h>
#include <math.h>

// Problem constants
#define BB 8
#define CC 64
#define NN 256
#define M1 20
#define M2 20
#define RR 40            // 2*M1 retained x-modes
#define MODES 800        // RR*M2
#define LL 3
#define FCN 128

// ---------------- device scratch (no allocs allowed) ----------------
__device__ float g_h[BB * CC * NN * NN];           // 128 MB, in-place layer state (b,c,x,y)
__device__ float g_t1[BB * CC * RR * NN];          // stage-1 DCT temp (bc, r, y)
__device__ float g_spec[MODES * BB * CC];          // forward spectrum, mode-major [m][b][c]
__device__ float g_spec2[BB * CC * MODES];         // mixed spectrum [b][o][m]
__device__ float g_t2[BB * CC * NN * M2];          // inverse stage-1 temp [b][o][x][s]
__device__ float g_Wm[LL * MODES * CC * CC];       // mode-major spectral weights [l][m][i*64+o]
__device__ float g_F1[RR * NN];                    // forward basis (x-axis), c_x baked in
__device__ float g_F2[M2 * NN];                    // forward basis (y-axis)
__device__ float g_G1[NN * RR];                    // inverse basis (x-axis), c_k baked in
__device__ float g_G2[NN * M2];                    // inverse basis (y-axis)

// ---------------- DCT basis tables ----------------
__global__ void k_init() {
    int x = blockIdx.x;      // 0..255
    int t = threadIdx.x;     // 0..255
    if (t < RR) {
        int k = (t < M1) ? t : (216 + t);               // {0..19} U {236..255}
        int m = (k * x) % 510;                          // cos period exact reduction
        float cv = (float)cospi((double)m / 255.0);
        float cx = (x == 0 || x == 255) ? 1.f : 2.f;    // forward input weight
        g_F1[t * NN + x] = cx * cv;
        float ck = (k == 0 || k == 255) ? 1.f : 2.f;    // inverse input weight
        g_G1[x * RR + t] = ck * cv;
    }
    if (t < M2) {
        int m = (t * x) % 510;
        float cv = (float)cospi((double)m / 255.0);
        float cy = (x == 0 || x == 255) ? 1.f : 2.f;
        g_F2[t * NN + x] = cy * cv;
        float cs = (t == 0) ? 1.f : 2.f;
        g_G2[x * M2 + t] = cs * cv;
    }
}

// ---------------- spectral weight transpose: (i,o,r,s) -> mode-major (r,s)(i,o) ----------------
__global__ void k_wtrans(const float* __restrict__ w1, const float* __restrict__ w2) {
    __shared__ float tile[32][33];
    int l = blockIdx.z >> 1, half = blockIdx.z & 1;
    const float* src = (half ? w2 : w1) + (size_t)l * CC * CC * (M1 * M2);   // [io=4096][400]
    float* dst = g_Wm + ((size_t)l * MODES + half * 400) * (CC * CC);        // [400][4096]
    int col = blockIdx.x * 32 + threadIdx.x;   // mode dim (0..399)
    int row = blockIdx.y * 32 + threadIdx.y;   // io dim (0..4095)
    if (col < 400) tile[threadIdx.y][threadIdx.x] = src[(size_t)row * 400 + col];
    __syncthreads();
    int drow = blockIdx.x * 32 + threadIdx.y;  // mode
    int dcol = blockIdx.y * 32 + threadIdx.x;  // io
    if (drow < 400) dst[(size_t)drow * 4096 + dcol] = tile[threadIdx.x][threadIdx.y];
}

// ---------------- fc0: x(B,X,Y,3) @ w(3,64) + b -> h(b,c,x,y) ----------------
__global__ void k_fc0(const float* __restrict__ x, const float* __restrict__ w,
                      const float* __restrict__ bias) {
    __shared__ float sw[3][CC];
    __shared__ float sb[CC];
    int xi = blockIdx.x, b = blockIdx.y, y = threadIdx.x;
    if (y < CC) { sw[0][y] = w[y]; sw[1][y] = w[CC + y]; sw[2][y] = w[2 * CC + y]; sb[y] = bias[y]; }
    __syncthreads();
    const float* xp = x + (((size_t)b * NN + xi) * NN + y) * 3;
    float d0 = xp[0], d1 = xp[1], d2 = xp[2];
    float* hp = g_h + ((size_t)(b * CC) * NN + xi) * NN + y;
#pragma unroll
    for (int c = 0; c < CC; c++)
        hp[(size_t)c * (NN * NN)] = sb[c] + d0 * sw[0][c] + d1 * sw[1][c] + d2 * sw[2][c];
}

// ---------------- forward DCT stage 1: t1[bc][r][y] = sum_x F1[r][x] h[bc][x][y] ----------------
__global__ __launch_bounds__(256) void k_stage1() {
    __shared__ float4 sF1[RR * 64];
    int bc = blockIdx.x, y = threadIdx.x;
    const float4* F14 = (const float4*)g_F1;
    for (int i = y; i < RR * 64; i += 256) sF1[i] = F14[i];
    __syncthreads();
    float acc[RR];
#pragma unroll
    for (int r = 0; r < RR; r++) acc[r] = 0.f;
    const float* hp = g_h + (size_t)bc * (NN * NN) + y;
    for (int x4 = 0; x4 < 64; x4++) {
        float h0 = hp[(x4 * 4 + 0) * NN];
        float h1 = hp[(x4 * 4 + 1) * NN];
        float h2 = hp[(x4 * 4 + 2) * NN];
        float h3 = hp[(x4 * 4 + 3) * NN];
#pragma unroll
        for (int r = 0; r < RR; r++) {
            float4 f = sF1[r * 64 + x4];
            acc[r] += f.x * h0 + f.y * h1 + f.z * h2 + f.w * h3;
        }
    }
    float* tp = g_t1 + (size_t)bc * (RR * NN) + y;
#pragma unroll
    for (int r = 0; r < RR; r++) tp[r * NN] = acc[r];
}

// ---------------- forward DCT stage 2: spec[m][b][c] = sum_y t1[bc][r][y] F2[s][y] ----------------
__global__ __launch_bounds__(256) void k_stage2() {
    __shared__ float4 sT[RR * 64];
    int bc = blockIdx.x, t = threadIdx.x;
    const float4* t14 = (const float4*)(g_t1 + (size_t)bc * (RR * NN));
    for (int i = t; i < RR * 64; i += 256) sT[i] = t14[i];
    __syncthreads();
    if (t < 200) {
        int a = t / 5, q = t % 5;     // a = r-mode, q = s-quad
        float4 acc = make_float4(0.f, 0.f, 0.f, 0.f);
        const float4* F24 = (const float4*)g_F2;
        for (int y4 = 0; y4 < 64; y4++) {
            float4 tv = sT[a * 64 + y4];
            float4 f0 = __ldg(&F24[(4 * q + 0) * 64 + y4]);
            float4 f1 = __ldg(&F24[(4 * q + 1) * 64 + y4]);
            float4 f2 = __ldg(&F24[(4 * q + 2) * 64 + y4]);
            float4 f3 = __ldg(&F24[(4 * q + 3) * 64 + y4]);
            acc.x += tv.x * f0.x + tv.y * f0.y + tv.z * f0.z + tv.w * f0.w;
            acc.y += tv.x * f1.x + tv.y * f1.y + tv.z * f1.z + tv.w * f1.w;
            acc.z += tv.x * f2.x + tv.y * f2.y + tv.z * f2.z + tv.w * f2.w;
            acc.w += tv.x * f3.x + tv.y * f3.y + tv.z * f3.z + tv.w * f3.w;
        }
        int m0 = a * M2 + 4 * q;
        g_spec[(size_t)(m0 + 0) * (BB * CC) + bc] = acc.x;
        g_spec[(size_t)(m0 + 1) * (BB * CC) + bc] = acc.y;
        g_spec[(size_t)(m0 + 2) * (BB * CC) + bc] = acc.z;
        g_spec[(size_t)(m0 + 3) * (BB * CC) + bc] = acc.w;
    }
}

// ---------------- per-mode channel mix: spec2[b][o][m] = sum_i spec[m][b][i] Wm[l][m][i][o] ----
__global__ __launch_bounds__(256) void k_mix(int l) {
    __shared__ float sW[CC * CC];
    __shared__ float sS[BB * CC];
    int m = blockIdx.x, t = threadIdx.x;
    const float* Wp = g_Wm + ((size_t)l * MODES + m) * (CC * CC);
    for (int i = t; i < CC * CC; i += 256) sW[i] = Wp[i];
    for (int i = t; i < BB * CC; i += 256) sS[i] = g_spec[(size_t)m * (BB * CC) + i];
    __syncthreads();
#pragma unroll
    for (int k = 0; k < 2; k++) {
        int idx = t + k * 256;
        int b = idx >> 6, o = idx & 63;
        float acc = 0.f;
#pragma unroll
        for (int i = 0; i < CC; i++) acc += sS[b * CC + i] * sW[i * CC + o];
        g_spec2[(size_t)(b * CC + o) * MODES + m] = acc;
    }
}

// ---------------- inverse stage 1: t2[bo][x][s] = sum_r G1[x][r] spec2[bo][r][s] ----------------
__global__ __launch_bounds__(256) void k_istage1() {
    __shared__ float sS[MODES];
    int bo = blockIdx.x, x = threadIdx.x;
    for (int i = x; i < MODES; i += 256) sS[i] = g_spec2[(size_t)bo * MODES + i];
    __syncthreads();
    float g1r[RR];
    const float4* gp = (const float4*)(g_G1 + x * RR);
#pragma unroll
    for (int j = 0; j < RR / 4; j++) {
        float4 v = gp[j];
        g1r[4 * j] = v.x; g1r[4 * j + 1] = v.y; g1r[4 * j + 2] = v.z; g1r[4 * j + 3] = v.w;
    }
    float acc[M2];
#pragma unroll
    for (int s = 0; s < M2; s++) acc[s] = 0.f;
#pragma unroll 4
    for (int r = 0; r < RR; r++) {
        float g = g1r[r];
#pragma unroll
        for (int s = 0; s < M2; s++) acc[s] += g * sS[r * M2 + s];
    }
    float* tp = g_t2 + ((size_t)bo * NN + x) * M2;
#pragma unroll
    for (int s = 0; s < M2; s++) tp[s] = acc[s];
}

// ---------------- fused: h = [tanh]( G1·spec2·G2^T + conv1x1(h) + bias ), in place -----------
__global__ __launch_bounds__(256, 2) void k_ilayer(const float* __restrict__ conv_w,
                                                   const float* __restrict__ conv_b,
                                                   int l, int do_tanh) {
    __shared__ float sCWT[CC * CC];      // [i][o]
    __shared__ float4 sT2[CC * 5];       // [o][s-quad]
    int xi = blockIdx.x, b = blockIdx.y, y = threadIdx.x;
    const float* cw = conv_w + (size_t)l * CC * CC;  // [o][i]
    for (int idx = y; idx < CC * CC; idx += 256) {
        int i = idx >> 6, o = idx & 63;
        sCWT[idx] = cw[o * CC + i];
    }
    float* st2f = (float*)sT2;
    for (int idx = y; idx < CC * M2; idx += 256) {
        int o = idx / M2, s = idx % M2;
        st2f[o * M2 + s] = g_t2[(((size_t)(b * CC + o)) * NN + xi) * M2 + s];
    }
    __syncthreads();

    float acc[CC];
#pragma unroll
    for (int o = 0; o < CC; o++) acc[o] = conv_b[l * CC + o];

    const float* hp = g_h + ((size_t)(b * CC) * NN + xi) * NN + y;
    const float4* cw4 = (const float4*)sCWT;
#pragma unroll 2
    for (int i = 0; i < CC; i++) {
        float hv = hp[(size_t)i * (NN * NN)];
#pragma unroll
        for (int o4 = 0; o4 < 16; o4++) {
            float4 w = cw4[i * 16 + o4];
            acc[o4 * 4 + 0] += w.x * hv;
            acc[o4 * 4 + 1] += w.y * hv;
            acc[o4 * 4 + 2] += w.z * hv;
            acc[o4 * 4 + 3] += w.w * hv;
        }
    }

    // inverse DCT along y: + sum_s t2[o][s] * G2[y][s]
    float g2r[M2];
    const float4* g2p = (const float4*)(g_G2 + y * M2);
#pragma unroll
    for (int j = 0; j < 5; j++) {
        float4 v = g2p[j];
        g2r[4 * j] = v.x; g2r[4 * j + 1] = v.y; g2r[4 * j + 2] = v.z; g2r[4 * j + 3] = v.w;
    }
#pragma unroll
    for (int o = 0; o < CC; o++) {
        float s = 0.f;
#pragma unroll
        for (int j = 0; j < 5; j++) {
            float4 tv = sT2[o * 5 + j];
            s += tv.x * g2r[4 * j] + tv.y * g2r[4 * j + 1] + tv.z * g2r[4 * j + 2] + tv.w * g2r[4 * j + 3];
        }
        acc[o] += s;
    }

    float* op = g_h + ((size_t)(b * CC) * NN + xi) * NN + y;
    if (do_tanh) {
#pragma unroll
        for (int o = 0; o < CC; o++) op[(size_t)o * (NN * NN)] = tanhf(acc[o]);
    } else {
#pragma unroll
        for (int o = 0; o < CC; o++) op[(size_t)o * (NN * NN)] = acc[o];
    }
}

// ---------------- fc1 (tanh) + fc2 fused ----------------
__global__ __launch_bounds__(256, 2) void k_fc12(const float* __restrict__ w1,
                                                 const float* __restrict__ b1,
                                                 const float* __restrict__ w2,
                                                 const float* __restrict__ b2,
                                                 float* __restrict__ out) {
    __shared__ float sW1[FCN * CC];   // [f][c]
    __shared__ float sB1[FCN];
    __shared__ float sW2[FCN];
    int xi = blockIdx.x, b = blockIdx.y, y = threadIdx.x;
    for (int idx = y; idx < FCN * CC; idx += 256) {
        int f = idx >> 6, c = idx & 63;
        sW1[idx] = w1[c * FCN + f];
    }
    if (y < FCN) { sB1[y] = b1[y]; sW2[y] = w2[y]; }
    __syncthreads();

    float hv[CC];
    const float* hp = g_h + ((size_t)(b * CC) * NN + xi) * NN + y;
#pragma unroll
    for (int c = 0; c < CC; c++) hv[c] = hp[(size_t)c * (NN * NN)];

    float accum = 0.f;
    const float4* w14 = (const float4*)sW1;
#pragma unroll 2
    for (int f = 0; f < FCN; f++) {
        float v = sB1[f];
#pragma unroll
        for (int c4 = 0; c4 < 16; c4++) {
            float4 w = w14[f * 16 + c4];
            v += w.x * hv[4 * c4] + w.y * hv[4 * c4 + 1] + w.z * hv[4 * c4 + 2] + w.w * hv[4 * c4 + 3];
        }
        accum += tanhf(v) * sW2[f];
    }
    out[((size_t)b * NN + xi) * NN + y] = accum + b2[0];
}

// ---------------- launch ----------------
extern "C" void kernel_launch(void* const* d_in, const int* in_sizes, int n_in,
                              void* d_out, int out_size) {
    const float* x      = (const float*)d_in[0];
    const float* fc0_w  = (const float*)d_in[1];
    const float* fc0_b  = (const float*)d_in[2];
    const float* sp_w1  = (const float*)d_in[3];
    const float* sp_w2  = (const float*)d_in[4];
    const float* conv_w = (const float*)d_in[5];
    const float* conv_b = (const float*)d_in[6];
    const float* fc1_w  = (const float*)d_in[7];
    const float* fc1_b  = (const float*)d_in[8];
    const float* fc2_w  = (const float*)d_in[9];
    const float* fc2_b  = (const float*)d_in[10];
    float* out = (float*)d_out;

    k_init<<<NN, 256>>>();
    k_wtrans<<<dim3(13, 128, LL * 2), dim3(32, 32)>>>(sp_w1, sp_w2);
    k_fc0<<<dim3(NN, BB), 256>>>(x, fc0_w, fc0_b);

    for (int l = 0; l < LL; l++) {
        k_stage1<<<BB * CC, 256>>>();
        k_stage2<<<BB * CC, 256>>>();
        k_mix<<<MODES, 256>>>(l);
        k_istage1<<<BB * CC, 256>>>();
        k_ilayer<<<dim3(NN, BB), 256>>>(conv_w, conv_b, l, (l != LL - 1) ? 1 : 0);
    }

    k_fc12<<<dim3(NN, BB), 256>>>(fc1_w, fc1_b, fc2_w, fc2_b, out);
}